// round 4
// baseline (speedup 1.0000x reference)
#include <cuda_runtime.h>

#define BB 8
#define CC 256
#define HH 96
#define WW 96
#define HS 192
#define WS 192
#define OC 32
#define GG 4
#define CG 64   // CC/GG

typedef unsigned long long u64;

// Offset field scratch: [B][G][HS][WS] x float2 (x-offset, y-offset) interleaved
__device__ float g_off[BB * GG * HS * WS * 2];

#define FMA_F32X2(d, a, b) \
    asm("fma.rn.f32x2 %0, %1, %2, %0;" : "+l"(d) : "l"(a), "l"(b))
#define PACK_F32X2(out, lo, hi) \
    asm("mov.b64 %0, {%1, %2};" : "=l"(out) : "f"(lo), "f"(hi))
#define UNPACK_F32X2(lo, hi, in) \
    asm("mov.b64 {%0, %1}, %2;" : "=f"(lo), "=f"(hi) : "l"(in))

// ---------------------------------------------------------------------------
// Kernel 1: 1x1 conv (32 outputs over 256 channels) + tanh + pixel_shuffle(2)
// One thread = TWO horizontally adjacent low-res pixels (one LDG.64 per
// channel); weights broadcast from smem as f32x2 pairs; fma.rn.f32x2 accs.
// ---------------------------------------------------------------------------
__global__ __launch_bounds__(256) void conv_offset_kernel(
    const float* __restrict__ x, const float* __restrict__ w,
    const float* __restrict__ bias)
{
    __shared__ __align__(16) float wT[CC * OC];  // wT[c*32 + o]
    int tid = threadIdx.x;
    #pragma unroll
    for (int k = 0; k < (CC * OC) / 256; ++k) {
        int flat = tid + k * 256;
        int c = flat >> 5, o = flat & 31;
        wT[flat] = w[o * CC + c];
    }
    __syncthreads();

    int pp  = blockIdx.x * 256 + tid;       // pair index 0 .. B*H*W/2-1
    int b   = pp / (HH * WW / 2);
    int rem = pp - b * (HH * WW / 2);
    int h   = rem / (WW / 2);
    int wp0 = (rem - h * (WW / 2)) * 2;     // even column of the pair

    u64 acc0[OC / 2], acc1[OC / 2];
    #pragma unroll
    for (int q = 0; q < OC / 2; ++q) {
        PACK_F32X2(acc0[q], bias[2 * q], bias[2 * q + 1]);
        acc1[q] = acc0[q];
    }

    const float* xp = x + (b * CC) * (HH * WW) + h * WW + wp0;
    #pragma unroll 2
    for (int c = 0; c < CC; ++c) {
        float2 xv = __ldg((const float2*)(xp + c * (HH * WW)));
        u64 xx0, xx1;
        PACK_F32X2(xx0, xv.x, xv.x);
        PACK_F32X2(xx1, xv.y, xv.y);
        const ulonglong2* wrow = (const ulonglong2*)(wT + c * OC);
        #pragma unroll
        for (int q = 0; q < OC / 4; ++q) {
            ulonglong2 wv = wrow[q];          // broadcast LDS.128 = 2 f32x2 pairs
            FMA_F32X2(acc0[2 * q + 0], xx0, wv.x);
            FMA_F32X2(acc0[2 * q + 1], xx0, wv.y);
            FMA_F32X2(acc1[2 * q + 0], xx1, wv.x);
            FMA_F32X2(acc1[2 * q + 1], xx1, wv.y);
        }
    }

    // pixel_shuffle(2) + tanh + scatter into interleaved (x,y) offset field
    #pragma unroll
    for (int px = 0; px < 2; ++px) {
        const u64* acc = px ? acc1 : acc0;
        int wp = wp0 + px;
        #pragma unroll
        for (int q = 0; q < OC / 2; ++q) {
            float a0, a1;
            UNPACK_F32X2(a0, a1, acc[q]);
            #pragma unroll
            for (int s = 0; s < 2; ++s) {
                int o    = 2 * q + s;
                float v  = tanhf(s ? a1 : a0);
                int co   = o >> 2;          // 0..7  channel after shuffle
                int i    = (o >> 1) & 1;    // row sub-position
                int j    = o & 1;           // col sub-position
                int gidx = co >> 1;         // group 0..3
                int k    = co & 1;          // 0 = x-offset, 1 = y-offset
                int hs = 2 * h + i, ws = 2 * wp + j;
                g_off[((((b * GG + gidx) * HS + hs) * WS + ws) << 1) + k] = v;
            }
        }
    }
}

// ---------------------------------------------------------------------------
// Kernel 2: bilinear border grid_sample. One thread = 4 VERTICALLY adjacent
// output pixels (same ws). Warp spans only 32 output cols -> ~16 source cols
// (~64B) per LDG -> ~1 L1 wavefront per load instead of ~2.
// ---------------------------------------------------------------------------
__global__ __launch_bounds__(256) void gather_kernel(
    const float* __restrict__ x, float* __restrict__ out)
{
    const int tiles = (HS / 4 * WS) / 256;  // 36 blocks per (b,g)
    int bg   = blockIdx.x / tiles;          // 0..31 = b*4 + gidx
    int t    = (blockIdx.x - bg * tiles) * 256 + threadIdx.x;
    int hrow = t / WS;                      // 0..47
    int ws   = t - hrow * WS;               // lanes -> consecutive ws
    int hs0  = hrow * 4;
    int b    = bg >> 2;
    int gidx = bg & 3;

    int   i00[4], dx[4], dy[4];
    float w00[4], w01[4], w10[4], w11[4];
    #pragma unroll
    for (int j = 0; j < 4; ++j) {
        float2 off = ((const float2*)g_off)[(bg * HS + hs0 + j) * WS + ws];
        // grid math collapsed: gx = (base_x + 0.125*off + 1)*48 - 0.5
        float gx = (float)ws         * 0.5f - 0.25f + 6.0f * off.x;
        float gy = (float)(hs0 + j)  * 0.5f - 0.25f + 6.0f * off.y;
        gx = fminf(fmaxf(gx, 0.0f), (float)(WW - 1));
        gy = fminf(fmaxf(gy, 0.0f), (float)(HH - 1));
        int x0 = (int)gx;   // floor (gx >= 0)
        int y0 = (int)gy;
        float wx = gx - (float)x0;
        float wy = gy - (float)y0;
        dx[j]  = (x0 < WW - 1) ? 1  : 0;
        dy[j]  = (y0 < HH - 1) ? WW : 0;
        i00[j] = y0 * WW + x0;
        w00[j] = (1.0f - wx) * (1.0f - wy);
        w01[j] = wx * (1.0f - wy);
        w10[j] = (1.0f - wx) * wy;
        w11[j] = wx * wy;
    }

    const float* xp = x + (b * CC + gidx * CG) * (HH * WW);
    float*       op = out + ((b * CC + gidx * CG) * HS + hs0) * WS + ws;

    #pragma unroll 2
    for (int c = 0; c < CG; ++c) {
        #pragma unroll
        for (int j = 0; j < 4; ++j) {
            float v00 = __ldg(xp + i00[j]);
            float v01 = __ldg(xp + i00[j] + dx[j]);
            float v10 = __ldg(xp + i00[j] + dy[j]);
            float v11 = __ldg(xp + i00[j] + dy[j] + dx[j]);
            op[j * WS] = v00 * w00[j] + v01 * w01[j] + v10 * w10[j] + v11 * w11[j];
        }
        xp += HH * WW;
        op += HS * WS;
    }
}

extern "C" void kernel_launch(void* const* d_in, const int* in_sizes, int n_in,
                              void* d_out, int out_size) {
    const float* x    = (const float*)d_in[0];
    const float* w    = (const float*)d_in[1];
    const float* bias = (const float*)d_in[2];
    float* out        = (float*)d_out;

    conv_offset_kernel<<<(BB * HH * WW / 2) / 256, 256>>>(x, w, bias);
    gather_kernel<<<BB * GG * ((HS / 4 * WS) / 256), 256>>>(x, out);
}

// round 5
// speedup vs baseline: 1.2894x; 1.2894x over previous
#include <cuda_runtime.h>

#define BB 8
#define CC 256
#define HH 96
#define WW 96
#define HS 192
#define WS 192
#define OC 32
#define GG 4
#define CG 64   // CC/GG

typedef unsigned long long u64;

// Offset field scratch: [B][G][HS][WS] x float2 (x-offset, y-offset) interleaved
__device__ float g_off[BB * GG * HS * WS * 2];

#define FMA_F32X2(d, a, b) \
    asm("fma.rn.f32x2 %0, %1, %2, %0;" : "+l"(d) : "l"(a), "l"(b))
#define PACK_F32X2(out, lo, hi) \
    asm("mov.b64 %0, {%1, %2};" : "=l"(out) : "f"(lo), "f"(hi))
#define UNPACK_F32X2(lo, hi, in) \
    asm("mov.b64 {%0, %1}, %2;" : "=f"(lo), "=f"(hi) : "l"(in))

// ---------------------------------------------------------------------------
// Kernel 1: 1x1 conv (32 outputs over 256 channels) + tanh + pixel_shuffle(2)
// One thread = one low-res pixel. 8-deep register prefetch of x (MLP=8),
// fma.rn.f32x2 accumulators, weights broadcast from smem as f32x2 pairs.
// ---------------------------------------------------------------------------
__global__ __launch_bounds__(256) void conv_offset_kernel(
    const float* __restrict__ x, const float* __restrict__ w,
    const float* __restrict__ bias)
{
    __shared__ __align__(16) float wT[CC * OC];  // wT[c*32 + o]
    int tid = threadIdx.x;
    #pragma unroll
    for (int k = 0; k < (CC * OC) / 256; ++k) {
        int flat = tid + k * 256;
        int c = flat >> 5, o = flat & 31;
        wT[flat] = w[o * CC + c];
    }
    __syncthreads();

    int p   = blockIdx.x * 256 + tid;       // 0 .. B*H*W-1 (73728)
    int b   = p / (HH * WW);
    int rem = p - b * (HH * WW);
    int h   = rem / WW;
    int wp  = rem - h * WW;

    u64 acc[OC / 2];
    #pragma unroll
    for (int q = 0; q < OC / 2; ++q)
        PACK_F32X2(acc[q], bias[2 * q], bias[2 * q + 1]);

    const float* xp = x + (b * CC) * (HH * WW) + h * WW + wp;
    #pragma unroll 1
    for (int c0 = 0; c0 < CC; c0 += 8) {
        float xv[8];
        #pragma unroll
        for (int u = 0; u < 8; ++u)                 // 8 independent LDGs
            xv[u] = __ldg(xp + (c0 + u) * (HH * WW));
        #pragma unroll
        for (int u = 0; u < 8; ++u) {
            u64 xx;
            PACK_F32X2(xx, xv[u], xv[u]);
            const ulonglong2* wrow = (const ulonglong2*)(wT + (c0 + u) * OC);
            #pragma unroll
            for (int q = 0; q < OC / 4; ++q) {
                ulonglong2 wv = wrow[q];            // broadcast LDS.128
                FMA_F32X2(acc[2 * q + 0], xx, wv.x);
                FMA_F32X2(acc[2 * q + 1], xx, wv.y);
            }
        }
    }

    // pixel_shuffle(2) + tanh + scatter into interleaved (x,y) offset field
    #pragma unroll
    for (int q = 0; q < OC / 2; ++q) {
        float a0, a1;
        UNPACK_F32X2(a0, a1, acc[q]);
        #pragma unroll
        for (int s = 0; s < 2; ++s) {
            int o    = 2 * q + s;
            float v  = tanhf(s ? a1 : a0);
            int co   = o >> 2;          // 0..7  channel after shuffle
            int i    = (o >> 1) & 1;    // row sub-position
            int j    = o & 1;           // col sub-position
            int gidx = co >> 1;         // group 0..3
            int k    = co & 1;          // 0 = x-offset, 1 = y-offset
            int hs = 2 * h + i, ws = 2 * wp + j;
            g_off[((((b * GG + gidx) * HS + hs) * WS + ws) << 1) + k] = v;
        }
    }
}

// ---------------------------------------------------------------------------
// Kernel 2: bilinear border grid_sample. One thread = 2 horizontally adjacent
// output pixels -> STG.64 streaming stores (halves store issue cost), one
// LDG.128 for both offset pairs, loads batched for MLP. Warp spans 64 output
// cols = ~32 source cols, keeping ~1 L1 line per gather load.
// ---------------------------------------------------------------------------
__global__ __launch_bounds__(256) void gather_kernel(
    const float* __restrict__ x, float* __restrict__ out)
{
    const int tiles = (HS * WS / 2) / 256;  // 72 pair-tiles per (b,g)
    int bg   = blockIdx.x / tiles;          // 0..31 = b*4 + gidx
    int t    = (blockIdx.x - bg * tiles) * 256 + threadIdx.x;
    int hs   = t / (WS / 2);
    int ws0  = (t - hs * (WS / 2)) * 2;     // even column of the pair
    int b    = bg >> 2;
    int gidx = bg & 3;

    // both offset pairs in one LDG.128: (x0,y0,x1,y1)
    float4 oo = __ldg((const float4*)g_off + (((bg * HS + hs) * WS + ws0) >> 1));
    float offx[2] = {oo.x, oo.z};
    float offy[2] = {oo.y, oo.w};

    int   i00[2], dx[2], dy[2];
    float w00[2], w01[2], w10[2], w11[2];
    #pragma unroll
    for (int j = 0; j < 2; ++j) {
        // grid math collapsed: gx = (base_x + 0.125*off + 1)*48 - 0.5
        float gx = (float)(ws0 + j) * 0.5f - 0.25f + 6.0f * offx[j];
        float gy = (float)hs        * 0.5f - 0.25f + 6.0f * offy[j];
        gx = fminf(fmaxf(gx, 0.0f), (float)(WW - 1));
        gy = fminf(fmaxf(gy, 0.0f), (float)(HH - 1));
        int x0 = (int)gx;   // floor (gx >= 0)
        int y0 = (int)gy;
        float wx = gx - (float)x0;
        float wy = gy - (float)y0;
        dx[j]  = (x0 < WW - 1) ? 1  : 0;
        dy[j]  = (y0 < HH - 1) ? WW : 0;
        i00[j] = y0 * WW + x0;
        w00[j] = (1.0f - wx) * (1.0f - wy);
        w01[j] = wx * (1.0f - wy);
        w10[j] = (1.0f - wx) * wy;
        w11[j] = wx * wy;
    }

    const float* xp = x + (b * CC + gidx * CG) * (HH * WW);
    float*       op = out + ((b * CC + gidx * CG) * HS + hs) * WS + ws0;

    #pragma unroll 2
    for (int c = 0; c < CG; ++c) {
        float v[8];
        #pragma unroll
        for (int j = 0; j < 2; ++j) {               // 8 independent LDGs
            v[4 * j + 0] = __ldg(xp + i00[j]);
            v[4 * j + 1] = __ldg(xp + i00[j] + dx[j]);
            v[4 * j + 2] = __ldg(xp + i00[j] + dy[j]);
            v[4 * j + 3] = __ldg(xp + i00[j] + dy[j] + dx[j]);
        }
        float2 r;
        r.x = v[0] * w00[0] + v[1] * w01[0] + v[2] * w10[0] + v[3] * w11[0];
        r.y = v[4] * w00[1] + v[5] * w01[1] + v[6] * w10[1] + v[7] * w11[1];
        __stcs((float2*)op, r);                     // streaming store
        xp += HH * WW;
        op += HS * WS;
    }
}

extern "C" void kernel_launch(void* const* d_in, const int* in_sizes, int n_in,
                              void* d_out, int out_size) {
    const float* x    = (const float*)d_in[0];
    const float* w    = (const float*)d_in[1];
    const float* bias = (const float*)d_in[2];
    float* out        = (float*)d_out;

    conv_offset_kernel<<<(BB * HH * WW) / 256, 256>>>(x, w, bias);
    gather_kernel<<<BB * GG * ((HS * WS / 2) / 256), 256>>>(x, out);
}